// round 5
// baseline (speedup 1.0000x reference)
#include <cuda_runtime.h>
#include <cuda_bf16.h>

// ChannelPolyLayer: out[b,o,x,y] = sum_c coeffs[b,o,c] * prod_v img[b,v,x,y]^powers[c,v]
// DEGREE=3, NUM_VARS=3, NUM_OUT=3, NUM_COEFFS=20, BATCH=16, H=W=512.
//
// Monomial order from _generate_powers(3,3):
//  0:1  1:v0  2:v1  3:v2  4:v0^2  5:v0v1  6:v0v2  7:v1^2  8:v1v2  9:v2^2
// 10:v0^3 11:v0^2v1 12:v0^2v2 13:v0v1^2 14:v0v1v2 15:v0v2^2
// 16:v1^3 17:v1^2v2 18:v1v2^2 19:v2^3
//
// Nested Horner (19 packed FMAs/output/2-pixels) with fma.rn.f32x2.
// 2 float4 items per thread, 6 LDG.128 front-batched (MLP=6).
// R5: __launch_bounds__(256,4) caps regs at 64 -> 4 CTAs/SM. ptxas trades a
// few register-cached coefficient pairs for LDS.64 reloads (broadcast, cheap,
// hidden under the 4-way-ILP Horner chains) to buy back occupancy.

#define HW_PIX (512 * 512)
#define HW4 (HW_PIX / 4)
#define NBATCH 16
#define NCOEF 20

typedef unsigned long long ull;

__device__ __forceinline__ ull ffma2(ull a, ull b, ull c) {
    ull d;
    asm("fma.rn.f32x2 %0, %1, %2, %3;" : "=l"(d) : "l"(a), "l"(b), "l"(c));
    return d;
}

// Horner over a packed pair of pixels. c[] are {coeff,coeff} splat pairs.
__device__ __forceinline__ ull horner2(ull v0, ull v1, ull v2,
                                       const ull* __restrict__ c) {
    ull pA = ffma2(c[16], v1, c[7]);
    pA = ffma2(v1, pA, c[2]);
    pA = ffma2(v1, pA, c[0]);
    ull pB = ffma2(c[17], v1, c[8]);
    pB = ffma2(v1, pB, c[3]);
    ull pC = ffma2(c[18], v1, c[9]);
    ull C0 = ffma2(c[19], v2, pC);
    C0 = ffma2(C0, v2, pB);
    C0 = ffma2(C0, v2, pA);
    ull qA = ffma2(c[13], v1, c[5]);
    qA = ffma2(v1, qA, c[1]);
    ull qB = ffma2(c[14], v1, c[6]);
    ull C1 = ffma2(c[15], v2, qB);
    C1 = ffma2(C1, v2, qA);
    ull C2 = ffma2(c[11], v1, c[4]);
    C2 = ffma2(c[12], v2, C2);
    ull r = ffma2(c[10], v0, C2);
    r = ffma2(r, v0, C1);
    r = ffma2(r, v0, C0);
    return r;
}

__global__ __launch_bounds__(256, 4) void channel_poly_kernel(
    const float* __restrict__ img,     // (B, 3, H, W)
    const float* __restrict__ coeffs,  // (B, 3, 20)
    float* __restrict__ out)           // (B, 3, H, W)
{
    __shared__ ull sc2[3 * NCOEF];
    const int b = blockIdx.y;
    const int t = threadIdx.x;
    if (t < 3 * NCOEF) {
        ull u = (ull)__float_as_uint(coeffs[b * (3 * NCOEF) + t]);
        sc2[t] = u | (u << 32);  // splat {c, c}
    }
    __syncthreads();

    // Each block covers 512 float4s: item a at base+t, item b at base+256+t.
    const int ia = blockIdx.x * 512 + t;
    const int ib = ia + 256;

    const ulonglong2* __restrict__ in0 =
        reinterpret_cast<const ulonglong2*>(img + (size_t)b * 3 * HW_PIX);

    // Front-batch all 6 LDG.128 (MLP=6 per thread).
    const ulonglong2 a0 = in0[ia];
    const ulonglong2 a1 = in0[ia + HW4];
    const ulonglong2 a2 = in0[ia + 2 * HW4];
    const ulonglong2 b0 = in0[ib];
    const ulonglong2 b1 = in0[ib + HW4];
    const ulonglong2 b2 = in0[ib + 2 * HW4];

    ulonglong2* __restrict__ o =
        reinterpret_cast<ulonglong2*>(out + (size_t)b * 3 * HW_PIX);

#pragma unroll 1
    for (int oc = 0; oc < 3; oc++) {
        const ull* __restrict__ c = sc2 + oc * NCOEF;
        ulonglong2 ra, rb;
        ra.x = horner2(a0.x, a1.x, a2.x, c);
        ra.y = horner2(a0.y, a1.y, a2.y, c);
        rb.x = horner2(b0.x, b1.x, b2.x, c);
        rb.y = horner2(b0.y, b1.y, b2.y, c);
        o[ia + oc * HW4] = ra;
        o[ib + oc * HW4] = rb;
    }
}

extern "C" void kernel_launch(void* const* d_in, const int* in_sizes, int n_in,
                              void* d_out, int out_size) {
    const float* img = (const float*)d_in[0];     // (16,3,512,512)
    const float* coeffs = (const float*)d_in[1];  // (16,3,20)
    float* out = (float*)d_out;

    dim3 grid(HW4 / 512, NBATCH, 1);   // 128 x 16
    channel_poly_kernel<<<grid, 256>>>(img, coeffs, out);
}

// round 6
// speedup vs baseline: 1.4877x; 1.4877x over previous
#include <cuda_runtime.h>
#include <cuda_bf16.h>

// ChannelPolyLayer: out[b,o,x,y] = sum_c coeffs[b,o,c] * prod_v img[b,v,x,y]^powers[c,v]
// DEGREE=3, NUM_VARS=3, NUM_OUT=3, NUM_COEFFS=20, BATCH=16, H=W=512.
//
// Monomial order from _generate_powers(3,3):
//  0:1  1:v0  2:v1  3:v2  4:v0^2  5:v0v1  6:v0v2  7:v1^2  8:v1v2  9:v2^2
// 10:v0^3 11:v0^2v1 12:v0^2v2 13:v0v1^2 14:v0v1v2 15:v0v2^2
// 16:v1^3 17:v1^2v2 18:v1v2^2 19:v2^3
//
// Nested Horner (19 packed fma.rn.f32x2 per output per pixel-pair).
// R6: persistent CTAs (296 = 2/SM), one barrier total, all-batch coeffs in
// shared, grid-stride loop with 1-deep software prefetch so each warp keeps
// 6 LDG.128 in flight under its compute phase (kills the load/compute phase
// synchronization that bound R2-R5). No aggressive reg cap (R5 lesson).

#define HW_PIX (512 * 512)
#define PLANE4 (HW_PIX / 4)     // float4s per channel plane = 65536
#define HALF4  (PLANE4 / 2)     // 32768; item j covers float4s j and j+HALF4
#define NBATCH 16
#define NCOEF  20
#define NITEMS (NBATCH * HALF4) // 524288 work items
#define NCTA   296              // 148 SMs * 2

typedef unsigned long long ull;

__device__ __forceinline__ ull ffma2(ull a, ull b, ull c) {
    ull d;
    asm("fma.rn.f32x2 %0, %1, %2, %3;" : "=l"(d) : "l"(a), "l"(b), "l"(c));
    return d;
}

// Horner over a packed pair of pixels. c[] are {coeff,coeff} splat pairs.
__device__ __forceinline__ ull horner2(ull v0, ull v1, ull v2,
                                       const ull* __restrict__ c) {
    ull pA = ffma2(c[16], v1, c[7]);
    pA = ffma2(v1, pA, c[2]);
    pA = ffma2(v1, pA, c[0]);
    ull pB = ffma2(c[17], v1, c[8]);
    pB = ffma2(v1, pB, c[3]);
    ull pC = ffma2(c[18], v1, c[9]);
    ull C0 = ffma2(c[19], v2, pC);
    C0 = ffma2(C0, v2, pB);
    C0 = ffma2(C0, v2, pA);
    ull qA = ffma2(c[13], v1, c[5]);
    qA = ffma2(v1, qA, c[1]);
    ull qB = ffma2(c[14], v1, c[6]);
    ull C1 = ffma2(c[15], v2, qB);
    C1 = ffma2(C1, v2, qA);
    ull C2 = ffma2(c[11], v1, c[4]);
    C2 = ffma2(c[12], v2, C2);
    ull r = ffma2(c[10], v0, C2);
    r = ffma2(r, v0, C1);
    r = ffma2(r, v0, C0);
    return r;
}

__global__ __launch_bounds__(256, 2) void channel_poly_kernel(
    const float* __restrict__ img,     // (B, 3, H, W)
    const float* __restrict__ coeffs,  // (B, 3, 20)
    float* __restrict__ out)           // (B, 3, H, W)
{
    __shared__ ull sc2[NBATCH * 3 * NCOEF];   // 960 splat pairs, 7680 B
    const int t = threadIdx.x;
    for (int k = t; k < NBATCH * 3 * NCOEF; k += 256) {
        ull u = (ull)__float_as_uint(coeffs[k]);
        sc2[k] = u | (u << 32);               // splat {c, c}
    }
    __syncthreads();                           // the only barrier

    const ulonglong2* __restrict__ in =
        reinterpret_cast<const ulonglong2*>(img);
    ulonglong2* __restrict__ op = reinterpret_cast<ulonglong2*>(out);

    const int stride = NCTA * 256;
    int g = blockIdx.x * 256 + t;

    // Prefetch first item. (g < NITEMS for all threads: 75776 < 524288.)
    int b = g >> 15;
    size_t base = (size_t)b * (3 * PLANE4) + (g & (HALF4 - 1));
    ulonglong2 a0 = in[base],          a1 = in[base + PLANE4],
               a2 = in[base + 2 * PLANE4];
    ulonglong2 b0 = in[base + HALF4],  b1 = in[base + HALF4 + PLANE4],
               b2 = in[base + HALF4 + 2 * PLANE4];

#pragma unroll 1
    while (g < NITEMS) {
        // Issue next iteration's loads before computing (keeps 6 LDG in flight).
        const int gn = g + stride;
        const int gl = (gn < NITEMS) ? gn : g;   // clamp: safe addr, result unused
        const int bn = gl >> 15;
        const size_t basen = (size_t)bn * (3 * PLANE4) + (gl & (HALF4 - 1));
        const ulonglong2 na0 = in[basen],         na1 = in[basen + PLANE4],
                         na2 = in[basen + 2 * PLANE4];
        const ulonglong2 nb0 = in[basen + HALF4], nb1 = in[basen + HALF4 + PLANE4],
                         nb2 = in[basen + HALF4 + 2 * PLANE4];

        const ull* __restrict__ cb = sc2 + b * (3 * NCOEF);
#pragma unroll 1
        for (int oc = 0; oc < 3; oc++) {
            const ull* __restrict__ c = cb + oc * NCOEF;
            ulonglong2 ra, rb;
            ra.x = horner2(a0.x, a1.x, a2.x, c);
            ra.y = horner2(a0.y, a1.y, a2.y, c);
            rb.x = horner2(b0.x, b1.x, b2.x, c);
            rb.y = horner2(b0.y, b1.y, b2.y, c);
            op[base + oc * PLANE4] = ra;
            op[base + HALF4 + oc * PLANE4] = rb;
        }

        // Rotate pipeline.
        g = gn; b = bn; base = basen;
        a0 = na0; a1 = na1; a2 = na2;
        b0 = nb0; b1 = nb1; b2 = nb2;
    }
}

extern "C" void kernel_launch(void* const* d_in, const int* in_sizes, int n_in,
                              void* d_out, int out_size) {
    const float* img = (const float*)d_in[0];     // (16,3,512,512)
    const float* coeffs = (const float*)d_in[1];  // (16,3,20)
    float* out = (float*)d_out;

    channel_poly_kernel<<<NCTA, 256>>>(img, coeffs, out);
}